// round 5
// baseline (speedup 1.0000x reference)
#include <cuda_runtime.h>
#include <cstdint>

#define N_NODES 50000
#define N_EDGES 800000

// ---------------------------------------------------------------------------
// scratch (__device__ globals; no allocation allowed)
// ---------------------------------------------------------------------------
__device__ float g_bufA[(size_t)N_NODES * 128];
__device__ float g_bufB[(size_t)N_NODES * 128];
__device__ float g_bufC[(size_t)N_NODES * 64];
__device__ float g_inv [N_NODES];
__device__ int   g_degi[N_NODES];
__device__ int   g_cursor[N_NODES];
__device__ int   g_off [N_NODES];
__device__ int   g_csr [N_EDGES];

// ---------------------------------------------------------------------------
// CSR build
// ---------------------------------------------------------------------------
__global__ void k_count(const int* __restrict__ dst) {
    int e = blockIdx.x * blockDim.x + threadIdx.x;
    if (e < N_EDGES) atomicAdd(&g_degi[dst[e]], 1);
}

// single-block exclusive scan over 50000 degrees + inverse degree
__global__ void k_scan() {   // <<<1, 1024>>>
    __shared__ int wsum[32];
    const int t = threadIdx.x;
    const int PER = (N_NODES + 1023) / 1024;   // 49
    const int base = t * PER;

    int s = 0;
    for (int i = 0; i < PER; i++) {
        int g = base + i;
        if (g < N_NODES) s += g_degi[g];
    }
    int lane = t & 31, wid = t >> 5;
    int v = s;
    for (int d = 1; d < 32; d <<= 1) {
        int u = __shfl_up_sync(0xFFFFFFFFu, v, d);
        if (lane >= d) v += u;
    }
    if (lane == 31) wsum[wid] = v;
    __syncthreads();
    if (wid == 0) {
        int w = wsum[lane];
        for (int d = 1; d < 32; d <<= 1) {
            int u = __shfl_up_sync(0xFFFFFFFFu, w, d);
            if (lane >= d) w += u;
        }
        wsum[lane] = w;
    }
    __syncthreads();
    int ex = v - s + ((wid > 0) ? wsum[wid - 1] : 0);
    for (int i = 0; i < PER; i++) {
        int g = base + i;
        if (g < N_NODES) {
            int d = g_degi[g];
            g_off[g] = ex;
            g_inv[g] = 1.0f / fmaxf((float)d, 1.0f);
            ex += d;
        }
    }
}

__global__ void k_fill(const int* __restrict__ src, const int* __restrict__ dst) {
    int e = blockIdx.x * blockDim.x + threadIdx.x;
    if (e < N_EDGES) {
        int d = dst[e];
        int pos = atomicAdd(&g_cursor[d], 1);
        g_csr[g_off[d] + pos] = src[e];
    }
}

// ---------------------------------------------------------------------------
// fused layer (fp32): 256 threads, BN=8 nodes/block, ONE WARP PER NODE.
// Gather: 16 lanes cover a row (VPL float4 each); lane>>4 selects one of 2
// edges processed in parallel; unroll 4 -> 8 edges in flight per warp.
// Then GEMM out = relu(h @ W^T + b).
// ---------------------------------------------------------------------------
template <int F_IN, int F_OUT>
__global__ void __launch_bounds__(256)
k_flayer(const float* __restrict__ x,
         const float* __restrict__ W,
         const float* __restrict__ b,
         float* __restrict__ out) {
    constexpr int BN  = 8;
    constexpr int WP  = F_IN + 4;
    constexpr int VPL = F_IN / 64;            // float4s per lane (1 or 2)
    extern __shared__ float sm[];
    float* sW  = sm;                           // F_OUT * WP
    float* sIn = sm + F_OUT * WP;              // BN * F_IN

    const int t    = threadIdx.x;              // 0..255
    const int lane = t & 31;
    const int w    = t >> 5;                   // warp 0..7 = node index
    const int node0 = blockIdx.x * BN;

    // load W into smem (padded rows)
    for (int i = t; i < F_OUT * F_IN; i += 256) {
        int r = i / F_IN;
        int c = i - r * F_IN;
        sW[r * WP + c] = W[i];
    }

    // ---- gather: node n = node0 + w ----
    const int n   = node0 + w;
    const int beg = g_off[n];
    const int dg  = g_degi[n];
    const int sub = lane >> 4;      // which of 2 parallel edges
    const int cl  = lane & 15;      // column group within row

    float4 acc[VPL];
#pragma unroll
    for (int v = 0; v < VPL; v++) acc[v] = make_float4(0.f, 0.f, 0.f, 0.f);

    int j = 0;
#pragma unroll 4
    for (; j + 2 <= dg; j += 2) {
        int e = __ldg(&g_csr[beg + j + sub]);
        const float4* r = reinterpret_cast<const float4*>(x + (size_t)e * F_IN) + cl * VPL;
#pragma unroll
        for (int v = 0; v < VPL; v++) {
            float4 a = r[v];
            acc[v].x += a.x; acc[v].y += a.y; acc[v].z += a.z; acc[v].w += a.w;
        }
    }
    if (j < dg && sub == 0) {       // odd leftover edge
        int e = __ldg(&g_csr[beg + j]);
        const float4* r = reinterpret_cast<const float4*>(x + (size_t)e * F_IN) + cl * VPL;
#pragma unroll
        for (int v = 0; v < VPL; v++) {
            float4 a = r[v];
            acc[v].x += a.x; acc[v].y += a.y; acc[v].z += a.z; acc[v].w += a.w;
        }
    }
    // combine the two edge-halves (lanes cl and cl+16 hold partial sums)
#pragma unroll
    for (int v = 0; v < VPL; v++) {
        acc[v].x += __shfl_xor_sync(0xFFFFFFFFu, acc[v].x, 16);
        acc[v].y += __shfl_xor_sync(0xFFFFFFFFu, acc[v].y, 16);
        acc[v].z += __shfl_xor_sync(0xFFFFFFFFu, acc[v].z, 16);
        acc[v].w += __shfl_xor_sync(0xFFFFFFFFu, acc[v].w, 16);
    }

    if (sub == 0) {
        const float inv = g_inv[n];
        const float4* self = reinterpret_cast<const float4*>(x + (size_t)n * F_IN) + cl * VPL;
#pragma unroll
        for (int v = 0; v < VPL; v++) {
            float4 s = self[v];
            float4 o;
            o.x = acc[v].x * inv + s.x;
            o.y = acc[v].y * inv + s.y;
            o.z = acc[v].z * inv + s.z;
            o.w = acc[v].w * inv + s.w;
            reinterpret_cast<float4*>(sIn + w * F_IN)[cl * VPL + v] = o;
        }
    }
    __syncthreads();

    // ---- GEMM ----
    constexpr int R   = 256 / F_OUT;          // 2 or 4
    constexpr int NPT = BN / R;                // 4 or 2
    const int neuron  = t % F_OUT;
    const int nd0     = (t / F_OUT) * NPT;

    float a[NPT];
    const float bias = __ldg(&b[neuron]);
#pragma unroll
    for (int bn = 0; bn < NPT; bn++) a[bn] = bias;

    const float4* w4 = reinterpret_cast<const float4*>(sW + neuron * WP);
#pragma unroll 4
    for (int k4 = 0; k4 < F_IN / 4; k4++) {
        float4 wv = w4[k4];
#pragma unroll
        for (int bn = 0; bn < NPT; bn++) {
            float4 v = reinterpret_cast<const float4*>(sIn + (nd0 + bn) * F_IN)[k4];
            a[bn] += wv.x * v.x + wv.y * v.y + wv.z * v.z + wv.w * v.w;
        }
    }
#pragma unroll
    for (int bn = 0; bn < NPT; bn++)
        out[(size_t)(node0 + nd0 + bn) * F_OUT + neuron] = fmaxf(a[bn], 0.0f);
}

// ---------------------------------------------------------------------------
// fused heads: emb copy + next_event(64) + classes(10)
// ---------------------------------------------------------------------------
__global__ void k_heads(const float* __restrict__ x3,
                        const float* __restrict__ Wp, const float* __restrict__ bp,
                        const float* __restrict__ Wc, const float* __restrict__ bc,
                        float* __restrict__ out) {
    constexpr int F = 64, NH = 74, BN = 8, WP = F + 4;
    __shared__ float sW[NH * WP];
    __shared__ float sB[NH];
    __shared__ float sIn[BN * F];
    const int t = threadIdx.x;  // 128

    for (int i = t; i < 64 * F; i += 128) {
        int r = i / F, c = i - r * F;
        sW[r * WP + c] = Wp[i];
    }
    for (int i = t; i < 10 * F; i += 128) {
        int r = i / F, c = i - r * F;
        sW[(64 + r) * WP + c] = Wc[i];
    }
    if (t < 64) sB[t] = bp[t];
    else if (t < NH) sB[t] = bc[t - 64];

    const int node0 = blockIdx.x * BN;
    for (int i = t; i < BN * F; i += 128) sIn[i] = x3[(size_t)node0 * F + i];
    __syncthreads();

    for (int i = t; i < BN * F; i += 128) out[(size_t)node0 * F + i] = sIn[i];

    if (t < NH) {
        float acc[BN];
#pragma unroll
        for (int bn = 0; bn < BN; bn++) acc[bn] = sB[t];
        const float4* w4 = reinterpret_cast<const float4*>(sW + t * WP);
#pragma unroll
        for (int k4 = 0; k4 < F / 4; k4++) {
            float4 w = w4[k4];
#pragma unroll
            for (int bn = 0; bn < BN; bn++) {
                float4 v = reinterpret_cast<const float4*>(sIn + bn * F)[k4];
                acc[bn] += w.x * v.x + w.y * v.y + w.z * v.z + w.w * v.w;
            }
        }
#pragma unroll
        for (int bn = 0; bn < BN; bn++) {
            int n = node0 + bn;
            if (t < 64)
                out[(size_t)N_NODES * 64 + (size_t)n * 64 + t] = acc[bn];
            else
                out[(size_t)N_NODES * 128 + (size_t)n * 10 + (t - 64)] = acc[bn];
        }
    }
}

// ---------------------------------------------------------------------------
extern "C" void kernel_launch(void* const* d_in, const int* in_sizes, int n_in,
                              void* d_out, int out_size) {
    const float* x  = (const float*)d_in[0];
    const int*   ei = (const int*)d_in[1];
    const int* src = ei;
    const int* dst = ei + N_EDGES;
    const float* W1 = (const float*)d_in[2];
    const float* b1 = (const float*)d_in[3];
    const float* W2 = (const float*)d_in[4];
    const float* b2 = (const float*)d_in[5];
    const float* W3 = (const float*)d_in[6];
    const float* b3 = (const float*)d_in[7];
    const float* Wp = (const float*)d_in[8];
    const float* bp = (const float*)d_in[9];
    const float* Wc = (const float*)d_in[10];
    const float* bc = (const float*)d_in[11];
    float* out = (float*)d_out;

    constexpr int BN = 8;
    constexpr int NB = N_NODES / BN;  // 6250

    constexpr int SMEM_L1 = (128 * (64 + 4)  + BN * 64)  * 4;   // 36864
    constexpr int SMEM_L2 = (128 * (128 + 4) + BN * 128) * 4;   // 71680
    constexpr int SMEM_L3 = (64  * (128 + 4) + BN * 128) * 4;   // 37888

    // one-time setup on first (uncaptured, correctness) call; no API calls
    // during graph capture afterwards
    static int* degi_ptr = nullptr;
    static int* cursor_ptr = nullptr;
    if (!degi_ptr) {
        cudaGetSymbolAddress((void**)&degi_ptr, g_degi);
        cudaGetSymbolAddress((void**)&cursor_ptr, g_cursor);
        cudaFuncSetAttribute(k_flayer<128, 128>,
                             cudaFuncAttributeMaxDynamicSharedMemorySize, SMEM_L2);
    }

    // zero via memset nodes (frees the 4th kernel-launch slot for profiling)
    cudaMemsetAsync(degi_ptr,   0, N_NODES * sizeof(int), 0);
    cudaMemsetAsync(cursor_ptr, 0, N_NODES * sizeof(int), 0);

    // CSR build
    k_count<<<(N_EDGES + 255) / 256, 256>>>(dst);
    k_scan<<<1, 1024>>>();
    k_fill<<<(N_EDGES + 255) / 256, 256>>>(src, dst);

    // fused layers (fp32) — k_flayer<64,128> is the 4th kernel launch
    k_flayer<64, 128><<<NB, 256, SMEM_L1>>>(x,      W1, b1, g_bufA);
    k_flayer<128,128><<<NB, 256, SMEM_L2>>>(g_bufA, W2, b2, g_bufB);
    k_flayer<128, 64><<<NB, 256, SMEM_L3>>>(g_bufB, W3, b3, g_bufC);

    // heads
    k_heads<<<NB, 128>>>(g_bufC, Wp, bp, Wc, bc, out);
}

// round 6
// speedup vs baseline: 13.9432x; 13.9432x over previous
#include <cuda_runtime.h>
#include <cstdint>

#define N_NODES 50000
#define N_EDGES 800000
#define BN      8
#define NGROUPS (N_NODES / BN)          // 6250
#define NCHUNK  ((N_NODES + 255) / 256) // 196

// ---------------------------------------------------------------------------
// scratch (__device__ globals; no allocation allowed)
// ---------------------------------------------------------------------------
__device__ float g_bufA[(size_t)N_NODES * 128];
__device__ float g_bufB[(size_t)N_NODES * 128];
__device__ float g_bufC[(size_t)N_NODES * 64];
__device__ float g_inv [N_NODES];
__device__ int   g_degi[N_NODES];
__device__ int   g_cursor[N_NODES];
__device__ int   g_off [N_NODES];
__device__ int   g_csr [N_EDGES];
__device__ int   g_chunksum[256];
__device__ int   g_chunkpre[256];
__device__ unsigned g_cnt;
__device__ volatile unsigned g_gen;

// ---------------------------------------------------------------------------
// grid-wide barrier (sense via generation counter)
// ---------------------------------------------------------------------------
__device__ __forceinline__ void gbar(unsigned nb) {
    __syncthreads();
    if (threadIdx.x == 0) {
        __threadfence();
        unsigned my = g_gen;
        if (atomicAdd(&g_cnt, 1u) == nb - 1u) {
            g_cnt = 0u;
            __threadfence();
            g_gen = my + 1u;
        } else {
            while (g_gen == my) __nanosleep(32);
        }
        __threadfence();
    }
    __syncthreads();
}

// block-wide exclusive scan of one int per thread (256 threads)
__device__ __forceinline__ int block_exscan256(int v) {
    __shared__ int ws[8];
    const int t = threadIdx.x, lane = t & 31, wid = t >> 5;
    int s = v;
#pragma unroll
    for (int d = 1; d < 32; d <<= 1) {
        int u = __shfl_up_sync(0xFFFFFFFFu, s, d);
        if (lane >= d) s += u;
    }
    __syncthreads();                 // protect ws from previous use
    if (lane == 31) ws[wid] = s;
    __syncthreads();
    int wpre = 0;
#pragma unroll
    for (int k = 0; k < 8; k++) if (k < wid) wpre += ws[k];
    return s - v + wpre;             // exclusive prefix
}

// ---------------------------------------------------------------------------
// layer phase: gather mean + self -> smem, GEMM relu(h @ W^T + b)
// one warp per node, BN=8 nodes per group, grid-stride over groups
// ---------------------------------------------------------------------------
template <int F_IN, int F_OUT>
__device__ __forceinline__ void layer_phase(const float* __restrict__ x,
                                            const float* __restrict__ W,
                                            const float* __restrict__ b,
                                            float* __restrict__ out,
                                            unsigned nb, float* sm) {
    constexpr int WP  = F_IN + 4;
    constexpr int VPL = F_IN / 64;            // float4s per 16-lane slice
    float* sW  = sm;                           // F_OUT * WP
    float* sIn = sm + F_OUT * WP;              // BN * F_IN

    const int t    = threadIdx.x;
    const int lane = t & 31;
    const int w    = t >> 5;
    const int sub  = lane >> 4;
    const int cl   = lane & 15;

    __syncthreads();                           // smem free from previous phase
    for (int i = t; i < F_OUT * F_IN; i += 256) {
        int r = i / F_IN, c = i - r * F_IN;
        sW[r * WP + c] = W[i];
    }

    constexpr int R   = 256 / F_OUT;
    constexpr int NPT = BN / R;
    const int neuron  = t % F_OUT;
    const int nd0     = (t / F_OUT) * NPT;
    const float bias  = __ldg(&b[neuron]);
    const float4* w4  = reinterpret_cast<const float4*>(sW + neuron * WP);
    __syncthreads();

    for (int g = blockIdx.x; g < NGROUPS; g += nb) {
        const int node0 = g * BN;
        const int n   = node0 + w;
        const int beg = g_off[n];
        const int dg  = g_degi[n];

        float4 acc[VPL];
#pragma unroll
        for (int v = 0; v < VPL; v++) acc[v] = make_float4(0.f, 0.f, 0.f, 0.f);

        int j = 0;
#pragma unroll 4
        for (; j + 2 <= dg; j += 2) {
            int e = __ldg(&g_csr[beg + j + sub]);
            const float4* r = reinterpret_cast<const float4*>(x + (size_t)e * F_IN) + cl * VPL;
#pragma unroll
            for (int v = 0; v < VPL; v++) {
                float4 a = r[v];
                acc[v].x += a.x; acc[v].y += a.y; acc[v].z += a.z; acc[v].w += a.w;
            }
        }
        if (j < dg && sub == 0) {
            int e = __ldg(&g_csr[beg + j]);
            const float4* r = reinterpret_cast<const float4*>(x + (size_t)e * F_IN) + cl * VPL;
#pragma unroll
            for (int v = 0; v < VPL; v++) {
                float4 a = r[v];
                acc[v].x += a.x; acc[v].y += a.y; acc[v].z += a.z; acc[v].w += a.w;
            }
        }
#pragma unroll
        for (int v = 0; v < VPL; v++) {
            acc[v].x += __shfl_xor_sync(0xFFFFFFFFu, acc[v].x, 16);
            acc[v].y += __shfl_xor_sync(0xFFFFFFFFu, acc[v].y, 16);
            acc[v].z += __shfl_xor_sync(0xFFFFFFFFu, acc[v].z, 16);
            acc[v].w += __shfl_xor_sync(0xFFFFFFFFu, acc[v].w, 16);
        }
        if (sub == 0) {
            const float inv = g_inv[n];
            const float4* self = reinterpret_cast<const float4*>(x + (size_t)n * F_IN) + cl * VPL;
#pragma unroll
            for (int v = 0; v < VPL; v++) {
                float4 s = self[v];
                float4 o;
                o.x = acc[v].x * inv + s.x;
                o.y = acc[v].y * inv + s.y;
                o.z = acc[v].z * inv + s.z;
                o.w = acc[v].w * inv + s.w;
                reinterpret_cast<float4*>(sIn + w * F_IN)[cl * VPL + v] = o;
            }
        }
        __syncthreads();

        float a[NPT];
#pragma unroll
        for (int bn = 0; bn < NPT; bn++) a[bn] = bias;
#pragma unroll 4
        for (int k4 = 0; k4 < F_IN / 4; k4++) {
            float4 wv = w4[k4];
#pragma unroll
            for (int bn = 0; bn < NPT; bn++) {
                float4 v = reinterpret_cast<const float4*>(sIn + (nd0 + bn) * F_IN)[k4];
                a[bn] += wv.x * v.x + wv.y * v.y + wv.z * v.z + wv.w * v.w;
            }
        }
#pragma unroll
        for (int bn = 0; bn < NPT; bn++)
            out[(size_t)(node0 + nd0 + bn) * F_OUT + neuron] = fmaxf(a[bn], 0.0f);
        __syncthreads();             // before next gather overwrites sIn
    }
}

// ---------------------------------------------------------------------------
// heads phase: emb copy + next_event(64) + classes(10)
// ---------------------------------------------------------------------------
__device__ __forceinline__ void heads_phase(const float* __restrict__ x3,
                                            const float* __restrict__ Wp,
                                            const float* __restrict__ bp,
                                            const float* __restrict__ Wc,
                                            const float* __restrict__ bc,
                                            float* __restrict__ out,
                                            unsigned nb, float* sm) {
    constexpr int F = 64, NH = 74, WP = F + 4;
    float* sW  = sm;                   // NH*WP = 5032
    float* sB  = sm + NH * WP;         // 74 (+pad to 128)
    float* sIn = sB + 128;             // BN*F = 512

    const int t = threadIdx.x;
    __syncthreads();
    for (int i = t; i < 64 * F; i += 256) sW[(i / F) * WP + (i % F)] = Wp[i];
    for (int i = t; i < 10 * F; i += 256) sW[(64 + i / F) * WP + (i % F)] = Wc[i];
    if (t < 64) sB[t] = bp[t];
    else if (t < NH) sB[t] = bc[t - 64];
    __syncthreads();

    const int sub = t >> 7;            // 0/1 -> node half
    const int tt  = t & 127;

    for (int g = blockIdx.x; g < NGROUPS; g += nb) {
        const int node0 = g * BN;
        for (int i = t; i < BN * F; i += 256) {
            float v = x3[(size_t)node0 * F + i];
            sIn[i] = v;
            out[(size_t)node0 * F + i] = v;     // embeddings copy
        }
        __syncthreads();

        if (tt < NH) {
            float acc[4];
#pragma unroll
            for (int bn = 0; bn < 4; bn++) acc[bn] = sB[tt];
            const float4* w4 = reinterpret_cast<const float4*>(sW + tt * WP);
#pragma unroll
            for (int k4 = 0; k4 < F / 4; k4++) {
                float4 w = w4[k4];
#pragma unroll
                for (int bn = 0; bn < 4; bn++) {
                    float4 v = reinterpret_cast<const float4*>(sIn + (sub * 4 + bn) * F)[k4];
                    acc[bn] += w.x * v.x + w.y * v.y + w.z * v.z + w.w * v.w;
                }
            }
#pragma unroll
            for (int bn = 0; bn < 4; bn++) {
                int n = node0 + sub * 4 + bn;
                if (tt < 64)
                    out[(size_t)N_NODES * 64 + (size_t)n * 64 + tt] = acc[bn];
                else
                    out[(size_t)N_NODES * 128 + (size_t)n * 10 + (tt - 64)] = acc[bn];
            }
        }
        __syncthreads();
    }
}

// ---------------------------------------------------------------------------
// the one kernel
// ---------------------------------------------------------------------------
__global__ void __launch_bounds__(256)
k_mega(const float* __restrict__ x,
       const int* __restrict__ src, const int* __restrict__ dst,
       const float* __restrict__ W1, const float* __restrict__ b1,
       const float* __restrict__ W2, const float* __restrict__ b2,
       const float* __restrict__ W3, const float* __restrict__ b3,
       const float* __restrict__ Wp, const float* __restrict__ bp,
       const float* __restrict__ Wc, const float* __restrict__ bc,
       float* __restrict__ out) {
    extern __shared__ float sm[];
    const unsigned nb = gridDim.x;
    const int t = threadIdx.x;
    const int gtid = blockIdx.x * 256 + t;
    const int gstride = nb * 256;

    // P0: zero
    for (int i = gtid; i < N_NODES; i += gstride) { g_degi[i] = 0; g_cursor[i] = 0; }
    gbar(nb);
    // P1: count
    for (int e = gtid; e < N_EDGES; e += gstride) atomicAdd(&g_degi[dst[e]], 1);
    gbar(nb);
    // P2a: per-chunk exclusive scans (chunk = 256 nodes)
    for (int c = blockIdx.x; c < NCHUNK; c += nb) {
        int i = c * 256 + t;
        int v = (i < N_NODES) ? g_degi[i] : 0;
        int ex = block_exscan256(v);
        if (i < N_NODES) g_off[i] = ex;
        if (t == 255) g_chunksum[c] = ex + v;
    }
    gbar(nb);
    // P2b: scan chunk sums (block 0)
    if (blockIdx.x == 0) {
        int v = (t < NCHUNK) ? g_chunksum[t] : 0;
        int ex = block_exscan256(v);
        if (t < NCHUNK) g_chunkpre[t] = ex;
    }
    gbar(nb);
    // P2c: finalize offsets + inverse degree
    for (int i = gtid; i < N_NODES; i += gstride) {
        g_off[i] += g_chunkpre[i >> 8];
        g_inv[i] = 1.0f / fmaxf((float)g_degi[i], 1.0f);
    }
    gbar(nb);
    // P3: fill CSR
    for (int e = gtid; e < N_EDGES; e += gstride) {
        int d = dst[e];
        int pos = atomicAdd(&g_cursor[d], 1);
        g_csr[g_off[d] + pos] = src[e];
    }
    gbar(nb);
    // P4-P6: layers
    layer_phase<64, 128>(x,      W1, b1, g_bufA, nb, sm);
    gbar(nb);
    layer_phase<128, 128>(g_bufA, W2, b2, g_bufB, nb, sm);
    gbar(nb);
    layer_phase<128, 64>(g_bufB, W3, b3, g_bufC, nb, sm);
    gbar(nb);
    // P7: heads
    heads_phase(g_bufC, Wp, bp, Wc, bc, out, nb, sm);
}

// ---------------------------------------------------------------------------
extern "C" void kernel_launch(void* const* d_in, const int* in_sizes, int n_in,
                              void* d_out, int out_size) {
    const float* x  = (const float*)d_in[0];
    const int*   ei = (const int*)d_in[1];
    const int* src = ei;
    const int* dst = ei + N_EDGES;
    const float* W1 = (const float*)d_in[2];
    const float* b1 = (const float*)d_in[3];
    const float* W2 = (const float*)d_in[4];
    const float* b2 = (const float*)d_in[5];
    const float* W3 = (const float*)d_in[6];
    const float* b3 = (const float*)d_in[7];
    const float* Wp = (const float*)d_in[8];
    const float* bp = (const float*)d_in[9];
    const float* Wc = (const float*)d_in[10];
    const float* bc = (const float*)d_in[11];
    float* out = (float*)d_out;

    constexpr int SMEM = (128 * (128 + 4) + BN * 128) * 4;   // 71680 (max phase)

    static int grid = 0;
    if (grid == 0) {
        cudaFuncSetAttribute(k_mega, cudaFuncAttributeMaxDynamicSharedMemorySize, SMEM);
        int dev = 0, sms = 0, occ = 0;
        cudaGetDevice(&dev);
        cudaDeviceGetAttribute(&sms, cudaDevAttrMultiProcessorCount, dev);
        cudaOccupancyMaxActiveBlocksPerMultiprocessor(&occ, k_mega, 256, SMEM);
        if (occ < 1) occ = 1;
        grid = sms * occ;
    }

    k_mega<<<grid, 256, SMEM>>>(x, src, dst, W1, b1, W2, b2, W3, b3,
                                Wp, bp, Wc, bc, out);
}

// round 7
// speedup vs baseline: 15.0992x; 1.0829x over previous
#include <cuda_runtime.h>
#include <cstdint>

#define N_NODES 50000
#define N_EDGES 800000
#define NCHUNK  ((N_NODES + 255) / 256) // 196

// ---------------------------------------------------------------------------
// scratch (__device__ globals; no allocation allowed)
// ---------------------------------------------------------------------------
__device__ float g_bufA[(size_t)N_NODES * 128];
__device__ float g_bufB[(size_t)N_NODES * 128];
__device__ float g_bufC[(size_t)N_NODES * 64];
__device__ float g_inv [N_NODES];
__device__ int   g_degi[N_NODES];
__device__ int   g_cursor[N_NODES];
__device__ int   g_off [N_NODES];
__device__ int   g_csr [N_EDGES];
__device__ int   g_chunksum[256];
__device__ int   g_chunkpre[256];
__device__ unsigned g_cnt;
__device__ volatile unsigned g_gen;

// ---------------------------------------------------------------------------
// grid-wide barrier
// ---------------------------------------------------------------------------
__device__ __forceinline__ void gbar(unsigned nb) {
    __syncthreads();
    if (threadIdx.x == 0) {
        __threadfence();
        unsigned my = g_gen;
        if (atomicAdd(&g_cnt, 1u) == nb - 1u) {
            g_cnt = 0u;
            __threadfence();
            g_gen = my + 1u;
        } else {
            while (g_gen == my) __nanosleep(32);
        }
        __threadfence();
    }
    __syncthreads();
}

// block-wide exclusive scan of one int per thread (256 threads)
__device__ __forceinline__ int block_exscan256(int v) {
    __shared__ int ws[8];
    const int t = threadIdx.x, lane = t & 31, wid = t >> 5;
    int s = v;
#pragma unroll
    for (int d = 1; d < 32; d <<= 1) {
        int u = __shfl_up_sync(0xFFFFFFFFu, s, d);
        if (lane >= d) s += u;
    }
    __syncthreads();
    if (lane == 31) ws[wid] = s;
    __syncthreads();
    int wpre = 0;
#pragma unroll
    for (int k = 0; k < 8; k++) if (k < wid) wpre += ws[k];
    return s - v + wpre;
}

// ---------------------------------------------------------------------------
// layer phase: gather mean + self -> sIn, then register-tiled GEMM
//   sWt : W transposed [k][neuron]   (F_IN x F_OUT)
//   sIn : h rows       [node][k]     (BN x F_IN)
// Thread tile: 4 neurons x 4 nodes.  NQ = F_OUT/4 neuron-quads,
// MQ = 256/NQ node-quads -> BN = 4*MQ nodes per group.
// ---------------------------------------------------------------------------
template <int F_IN, int F_OUT>
__device__ __forceinline__ void layer_phase(const float* __restrict__ x,
                                            const float* __restrict__ W,
                                            const float* __restrict__ b,
                                            float* __restrict__ out,
                                            unsigned nb, float* sm) {
    constexpr int NQ  = F_OUT / 4;            // 32 or 16
    constexpr int MQ  = 256 / NQ;             // 8 or 16
    constexpr int BN  = MQ * 4;               // 32 or 64
    constexpr int NPW = BN / 8;               // nodes per warp in gather
    constexpr int NG  = (N_NODES + BN - 1) / BN;
    constexpr int VPL = F_IN / 64;            // float4s per 16-lane row slice

    float* sWt = sm;                           // F_IN * F_OUT
    float* sIn = sm + F_IN * F_OUT;            // BN * F_IN

    const int t    = threadIdx.x;
    const int lane = t & 31;
    const int w    = t >> 5;
    const int sub  = lane >> 4;
    const int cl   = lane & 15;

    __syncthreads();                           // previous phase done with sm
    // W transpose into smem: consecutive-bank writes, cached strided reads
    for (int i = t; i < F_IN * F_OUT; i += 256) {
        int r = i % F_OUT;                     // neuron
        int c = i / F_OUT;                     // k
        sWt[i] = __ldg(&W[r * F_IN + c]);
    }

    const int nq = t % NQ;
    const int mq = t / NQ;
    const float4 bv = __ldg(reinterpret_cast<const float4*>(b) + nq);
    __syncthreads();

    for (int g = blockIdx.x; g < NG; g += nb) {
        const int node0 = g * BN;

        // ---- gather: warp w handles NPW nodes serially ----
#pragma unroll
        for (int s = 0; s < NPW; s++) {
            const int nl = w * NPW + s;        // local node
            const int n  = node0 + nl;
            if (n < N_NODES) {
                const int beg = g_off[n];
                const int dg  = g_degi[n];
                float4 acc[VPL];
#pragma unroll
                for (int v = 0; v < VPL; v++) acc[v] = make_float4(0.f, 0.f, 0.f, 0.f);

                int j = 0;
#pragma unroll 4
                for (; j + 2 <= dg; j += 2) {
                    int e = __ldg(&g_csr[beg + j + sub]);
                    const float4* r = reinterpret_cast<const float4*>(x + (size_t)e * F_IN) + cl * VPL;
#pragma unroll
                    for (int v = 0; v < VPL; v++) {
                        float4 a = r[v];
                        acc[v].x += a.x; acc[v].y += a.y; acc[v].z += a.z; acc[v].w += a.w;
                    }
                }
                if (j < dg && sub == 0) {
                    int e = __ldg(&g_csr[beg + j]);
                    const float4* r = reinterpret_cast<const float4*>(x + (size_t)e * F_IN) + cl * VPL;
#pragma unroll
                    for (int v = 0; v < VPL; v++) {
                        float4 a = r[v];
                        acc[v].x += a.x; acc[v].y += a.y; acc[v].z += a.z; acc[v].w += a.w;
                    }
                }
#pragma unroll
                for (int v = 0; v < VPL; v++) {
                    acc[v].x += __shfl_xor_sync(0xFFFFFFFFu, acc[v].x, 16);
                    acc[v].y += __shfl_xor_sync(0xFFFFFFFFu, acc[v].y, 16);
                    acc[v].z += __shfl_xor_sync(0xFFFFFFFFu, acc[v].z, 16);
                    acc[v].w += __shfl_xor_sync(0xFFFFFFFFu, acc[v].w, 16);
                }
                if (sub == 0) {
                    const float inv = g_inv[n];
                    const float4* self = reinterpret_cast<const float4*>(x + (size_t)n * F_IN) + cl * VPL;
#pragma unroll
                    for (int v = 0; v < VPL; v++) {
                        float4 sv = self[v];
                        float4 o;
                        o.x = acc[v].x * inv + sv.x;
                        o.y = acc[v].y * inv + sv.y;
                        o.z = acc[v].z * inv + sv.z;
                        o.w = acc[v].w * inv + sv.w;
                        reinterpret_cast<float4*>(sIn + (size_t)nl * F_IN)[cl * VPL + v] = o;
                    }
                }
            }
        }
        __syncthreads();

        // ---- GEMM: 4x4 register tile ----
        float acc[4][4];
#pragma unroll
        for (int i = 0; i < 4; i++) {
            acc[i][0] = bv.x; acc[i][1] = bv.y; acc[i][2] = bv.z; acc[i][3] = bv.w;
        }
        const float4* wt4 = reinterpret_cast<const float4*>(sWt);
#pragma unroll 4
        for (int k0 = 0; k0 < F_IN; k0 += 4) {
            float4 wv[4];
#pragma unroll
            for (int j = 0; j < 4; j++) wv[j] = wt4[(size_t)(k0 + j) * NQ + nq];
            float4 vv[4];
#pragma unroll
            for (int i = 0; i < 4; i++)
                vv[i] = *reinterpret_cast<const float4*>(sIn + (size_t)(mq * 4 + i) * F_IN + k0);
#pragma unroll
            for (int i = 0; i < 4; i++) {
                acc[i][0] += vv[i].x * wv[0].x + vv[i].y * wv[1].x + vv[i].z * wv[2].x + vv[i].w * wv[3].x;
                acc[i][1] += vv[i].x * wv[0].y + vv[i].y * wv[1].y + vv[i].z * wv[2].y + vv[i].w * wv[3].y;
                acc[i][2] += vv[i].x * wv[0].z + vv[i].y * wv[1].z + vv[i].z * wv[2].z + vv[i].w * wv[3].z;
                acc[i][3] += vv[i].x * wv[0].w + vv[i].y * wv[1].w + vv[i].z * wv[2].w + vv[i].w * wv[3].w;
            }
        }
#pragma unroll
        for (int i = 0; i < 4; i++) {
            int n = node0 + mq * 4 + i;
            if (n < N_NODES) {
                float4 o;
                o.x = fmaxf(acc[i][0], 0.f);
                o.y = fmaxf(acc[i][1], 0.f);
                o.z = fmaxf(acc[i][2], 0.f);
                o.w = fmaxf(acc[i][3], 0.f);
                *reinterpret_cast<float4*>(out + (size_t)n * F_OUT + nq * 4) = o;
            }
        }
        __syncthreads();
    }
}

// ---------------------------------------------------------------------------
// heads phase: emb copy + next_event(64) + classes(10); BN=8, 256 threads
// ---------------------------------------------------------------------------
__device__ __forceinline__ void heads_phase(const float* __restrict__ x3,
                                            const float* __restrict__ Wp,
                                            const float* __restrict__ bp,
                                            const float* __restrict__ Wc,
                                            const float* __restrict__ bc,
                                            float* __restrict__ out,
                                            unsigned nb, float* sm) {
    constexpr int F = 64, NH = 74, WP = F + 4, NG8 = N_NODES / 8;
    float* sW  = sm;
    float* sB  = sm + NH * WP;
    float* sIn = sB + 128;

    const int t = threadIdx.x;
    __syncthreads();
    for (int i = t; i < 64 * F; i += 256) sW[(i / F) * WP + (i % F)] = Wp[i];
    for (int i = t; i < 10 * F; i += 256) sW[(64 + i / F) * WP + (i % F)] = Wc[i];
    if (t < 64) sB[t] = bp[t];
    else if (t < NH) sB[t] = bc[t - 64];
    __syncthreads();

    const int sub = t >> 7;
    const int tt  = t & 127;

    for (int g = blockIdx.x; g < NG8; g += nb) {
        const int node0 = g * 8;
        for (int i = t; i < 8 * F; i += 256) {
            float v = x3[(size_t)node0 * F + i];
            sIn[i] = v;
            out[(size_t)node0 * F + i] = v;
        }
        __syncthreads();

        if (tt < NH) {
            float acc[4];
#pragma unroll
            for (int bn = 0; bn < 4; bn++) acc[bn] = sB[tt];
            const float4* w4 = reinterpret_cast<const float4*>(sW + tt * WP);
#pragma unroll
            for (int k4 = 0; k4 < F / 4; k4++) {
                float4 w = w4[k4];
#pragma unroll
                for (int bn = 0; bn < 4; bn++) {
                    float4 v = reinterpret_cast<const float4*>(sIn + (sub * 4 + bn) * F)[k4];
                    acc[bn] += w.x * v.x + w.y * v.y + w.z * v.z + w.w * v.w;
                }
            }
#pragma unroll
            for (int bn = 0; bn < 4; bn++) {
                int n = node0 + sub * 4 + bn;
                if (tt < 64)
                    out[(size_t)N_NODES * 64 + (size_t)n * 64 + tt] = acc[bn];
                else
                    out[(size_t)N_NODES * 128 + (size_t)n * 10 + (tt - 64)] = acc[bn];
            }
        }
        __syncthreads();
    }
}

// ---------------------------------------------------------------------------
// the one kernel
// ---------------------------------------------------------------------------
__global__ void __launch_bounds__(256, 2)
k_mega(const float* __restrict__ x,
       const int* __restrict__ src, const int* __restrict__ dst,
       const float* __restrict__ W1, const float* __restrict__ b1,
       const float* __restrict__ W2, const float* __restrict__ b2,
       const float* __restrict__ W3, const float* __restrict__ b3,
       const float* __restrict__ Wp, const float* __restrict__ bp,
       const float* __restrict__ Wc, const float* __restrict__ bc,
       float* __restrict__ out) {
    extern __shared__ float sm[];
    const unsigned nb = gridDim.x;
    const int t = threadIdx.x;
    const int gtid = blockIdx.x * 256 + t;
    const int gstride = nb * 256;

    // P0: zero
    for (int i = gtid; i < N_NODES; i += gstride) { g_degi[i] = 0; g_cursor[i] = 0; }
    gbar(nb);
    // P1: count
    for (int e = gtid; e < N_EDGES; e += gstride) atomicAdd(&g_degi[dst[e]], 1);
    gbar(nb);
    // P2a: per-chunk exclusive scans
    for (int c = blockIdx.x; c < NCHUNK; c += nb) {
        int i = c * 256 + t;
        int v = (i < N_NODES) ? g_degi[i] : 0;
        int ex = block_exscan256(v);
        if (i < N_NODES) g_off[i] = ex;
        if (t == 255) g_chunksum[c] = ex + v;
    }
    gbar(nb);
    // P2b: scan chunk sums
    if (blockIdx.x == 0) {
        int v = (t < NCHUNK) ? g_chunksum[t] : 0;
        int ex = block_exscan256(v);
        if (t < NCHUNK) g_chunkpre[t] = ex;
    }
    gbar(nb);
    // P2c: finalize offsets + inverse degree
    for (int i = gtid; i < N_NODES; i += gstride) {
        g_off[i] += g_chunkpre[i >> 8];
        g_inv[i] = 1.0f / fmaxf((float)g_degi[i], 1.0f);
    }
    gbar(nb);
    // P3: fill CSR
    for (int e = gtid; e < N_EDGES; e += gstride) {
        int d = dst[e];
        int pos = atomicAdd(&g_cursor[d], 1);
        g_csr[g_off[d] + pos] = src[e];
    }
    gbar(nb);
    // P4-P6: layers
    layer_phase<64, 128>(x,      W1, b1, g_bufA, nb, sm);
    gbar(nb);
    layer_phase<128, 128>(g_bufA, W2, b2, g_bufB, nb, sm);
    gbar(nb);
    layer_phase<128, 64>(g_bufB, W3, b3, g_bufC, nb, sm);
    gbar(nb);
    // P7: heads
    heads_phase(g_bufC, Wp, bp, Wc, bc, out, nb, sm);
}

// ---------------------------------------------------------------------------
extern "C" void kernel_launch(void* const* d_in, const int* in_sizes, int n_in,
                              void* d_out, int out_size) {
    const float* x  = (const float*)d_in[0];
    const int*   ei = (const int*)d_in[1];
    const int* src = ei;
    const int* dst = ei + N_EDGES;
    const float* W1 = (const float*)d_in[2];
    const float* b1 = (const float*)d_in[3];
    const float* W2 = (const float*)d_in[4];
    const float* b2 = (const float*)d_in[5];
    const float* W3 = (const float*)d_in[6];
    const float* b3 = (const float*)d_in[7];
    const float* Wp = (const float*)d_in[8];
    const float* bp = (const float*)d_in[9];
    const float* Wc = (const float*)d_in[10];
    const float* bc = (const float*)d_in[11];
    float* out = (float*)d_out;

    // max phase smem: layer2 = (128*128 + 32*128)*4 = 81920 B
    constexpr int SMEM = (128 * 128 + 32 * 128) * 4;

    static int grid = 0;
    if (grid == 0) {
        cudaFuncSetAttribute(k_mega, cudaFuncAttributeMaxDynamicSharedMemorySize, SMEM);
        int dev = 0, sms = 0, occ = 0;
        cudaGetDevice(&dev);
        cudaDeviceGetAttribute(&sms, cudaDevAttrMultiProcessorCount, dev);
        cudaOccupancyMaxActiveBlocksPerMultiprocessor(&occ, k_mega, 256, SMEM);
        if (occ < 1) occ = 1;
        grid = sms * occ;
    }

    k_mega<<<grid, 256, SMEM>>>(x, src, dst, W1, b1, W2, b2, W3, b3,
                                Wp, bp, Wc, bc, out);
}